// round 3
// baseline (speedup 1.0000x reference)
#include <cuda_runtime.h>
#include <cuda_bf16.h>
#include <math.h>

// Problem constants (from reference)
#define N_NODES_MAX 100000
#define E_MAX       1600000
#define IN_C 128
#define H1   71
#define H2   82

// ------------------- device scratch (static, no allocation) -------------------
__device__ int   g_is64;
__device__ int   g_deg[N_NODES_MAX];
__device__ float g_dinv[N_NODES_MAX];
__device__ int   g_rowoff[N_NODES_MAX + 1];
__device__ int   g_cursor[N_NODES_MAX];
__device__ int   g_csr[E_MAX];
__device__ int   g_src[E_MAX];
__device__ int   g_dst[E_MAX];
__device__ float g_bufA[(size_t)N_NODES_MAX * H2];  // GEMM outputs (max dim 82)
__device__ float g_bufB[(size_t)N_NODES_MAX * H2];  // gather outputs

// ------------------- dtype sniff -------------------
// int64 edge indices < 1e5 have zero high words; int32 random indices do not.
__global__ void k_sniff(const int* __restrict__ ei32, int E) {
    if (threadIdx.x == 0 && blockIdx.x == 0) {
        int all0 = 1;
        int m = (E > 64) ? 64 : E;
        for (int i = 0; i < m; i++) {
            if (ei32[2 * i + 1] != 0) { all0 = 0; break; }
        }
        g_is64 = all0;
    }
}

// ------------------- small setup kernels -------------------
__global__ void k_init_deg(int n) {
    int i = blockIdx.x * blockDim.x + threadIdx.x;
    if (i < n) g_deg[i] = 0;
}

__global__ void k_deg_count(const void* __restrict__ ei, int E, int n) {
    int i = blockIdx.x * blockDim.x + threadIdx.x;
    if (i < E) {
        int s, d;
        if (g_is64) {
            s = (int)((const long long*)ei)[i];
            d = (int)((const long long*)ei)[(size_t)E + i];
        } else {
            s = ((const int*)ei)[i];
            d = ((const int*)ei)[(size_t)E + i];
        }
        // defensive clamp (should never fire on valid data)
        s = min(max(s, 0), n - 1);
        d = min(max(d, 0), n - 1);
        g_src[i] = s;
        g_dst[i] = d;
        atomicAdd(&g_deg[d], 1);
    }
}

__global__ void k_dinv(int n) {
    int i = blockIdx.x * blockDim.x + threadIdx.x;
    if (i < n) g_dinv[i] = rsqrtf((float)g_deg[i] + 1.0f);
}

// Single-block exclusive scan of g_deg -> g_rowoff, g_cursor. 1024 threads, 4 elems/thread/chunk.
__global__ void k_scan(int n) {
    __shared__ int wsum[32];
    __shared__ int s_carry;
    const int t = threadIdx.x, lane = t & 31, wid = t >> 5;
    if (t == 0) s_carry = 0;
    __syncthreads();
    const int CH = 4096;
    for (int base = 0; base < n; base += CH) {
        int i0 = base + t * 4;
        int v[4];
#pragma unroll
        for (int q = 0; q < 4; q++) {
            int i = i0 + q;
            v[q] = (i < n) ? g_deg[i] : 0;
        }
        int tsum = v[0] + v[1] + v[2] + v[3];
        int x = tsum;
#pragma unroll
        for (int off = 1; off < 32; off <<= 1) {
            int y = __shfl_up_sync(0xffffffffu, x, off);
            if (lane >= off) x += y;
        }
        if (lane == 31) wsum[wid] = x;
        __syncthreads();
        if (wid == 0) {
            int w = wsum[lane];
            int xx = w;
#pragma unroll
            for (int off = 1; off < 32; off <<= 1) {
                int y = __shfl_up_sync(0xffffffffu, xx, off);
                if (lane >= off) xx += y;
            }
            wsum[lane] = xx - w;  // exclusive
        }
        __syncthreads();
        int run = s_carry + wsum[wid] + (x - tsum);
#pragma unroll
        for (int q = 0; q < 4; q++) {
            int i = i0 + q;
            if (i < n) {
                g_rowoff[i] = run;
                g_cursor[i] = run;
            }
            run += v[q];
        }
        __syncthreads();
        if (t == 1023) s_carry += wsum[31] + x;  // chunk total
        __syncthreads();
    }
    if (t == 0) g_rowoff[n] = s_carry;
}

__global__ void k_fill(int E) {
    int i = blockIdx.x * blockDim.x + threadIdx.x;
    if (i < E) {
        int d = g_dst[i];
        int p = atomicAdd(&g_cursor[d], 1);
        g_csr[p] = g_src[i];
    }
}

// ------------------- GEMM: g_bufA[n,N] = X[n,K] @ W[K,N] -------------------
// X = kernel param if FROM_PARAM, else g_bufB. Output always g_bufA.
// 256 threads, 256 nodes per block, one node per thread, full-N accumulator in regs.
template <int K, int N, bool FROM_PARAM>
__global__ void __launch_bounds__(256)
k_gemm(const float* __restrict__ Xp, const float* __restrict__ W, int n) {
    constexpr int BM = 256, KK = 32;
    __shared__ float xs[KK][BM + 1];  // padded: conflict-free transposed access
    __shared__ float ws[KK][N];
    const float* X = FROM_PARAM ? Xp : (const float*)g_bufB;
    float* Y = g_bufA;
    const int t = threadIdx.x;
    const int node0 = blockIdx.x * BM;

    float acc[N];
#pragma unroll
    for (int j = 0; j < N; j++) acc[j] = 0.0f;

    for (int k0 = 0; k0 < K; k0 += KK) {
        const int kc = (K - k0 < KK) ? (K - k0) : KK;
        // load x tile (transposed into smem)
        for (int idx = t; idx < BM * KK; idx += 256) {
            int nl = idx >> 5;
            int kk = idx & 31;
            int node = node0 + nl;
            float v = 0.0f;
            if (kk < kc && node < n) v = X[(size_t)node * K + k0 + kk];
            xs[kk][nl] = v;
        }
        // load W chunk (contiguous)
        for (int idx = t; idx < KK * N; idx += 256) {
            int kk = idx / N;
            ws[kk][idx - kk * N] = (kk < kc) ? W[(size_t)k0 * N + idx] : 0.0f;
        }
        __syncthreads();
        for (int kk = 0; kk < KK; kk++) {
            float xv = xs[kk][t];
#pragma unroll
            for (int j = 0; j < N; j++) acc[j] += xv * ws[kk][j];
        }
        __syncthreads();
    }

    int node = node0 + t;
    if (node < n) {
#pragma unroll
        for (int j = 0; j < N; j++) Y[(size_t)node * N + j] = acc[j];
    }
}

// ------------------- gather aggregation: warp per node -------------------
// g_bufB[i,c] = dinv[i] * sum_{e in CSR(i)} dinv[src]*g_bufA[src,c]
//               + g_bufA[i,c]*dinv[i]^2 + b[c]   (optional relu)
template <int N, bool RELU>
__global__ void __launch_bounds__(256)
k_gather(const float* __restrict__ b, int n) {
    const int node = (blockIdx.x * blockDim.x + threadIdx.x) >> 5;
    if (node >= n) return;
    const int lane = threadIdx.x & 31;
    constexpr int NR = (N + 31) / 32;
    const float* xw = (const float*)g_bufA;
    float* out = (float*)g_bufB;

    float acc[NR];
#pragma unroll
    for (int r = 0; r < NR; r++) acc[r] = 0.0f;

    const int beg = g_rowoff[node];
    const int end = g_rowoff[node + 1];
    for (int e = beg; e < end; e++) {
        const int s = g_csr[e];
        const float w = g_dinv[s];
        const float* row = xw + (size_t)s * N;
#pragma unroll
        for (int r = 0; r < NR; r++) {
            int c = lane + 32 * r;
            if (c < N) acc[r] += w * __ldg(row + c);
        }
    }
    const float di = g_dinv[node];
    const float self = di * di;
    const float* myrow = xw + (size_t)node * N;
#pragma unroll
    for (int r = 0; r < NR; r++) {
        int c = lane + 32 * r;
        if (c < N) {
            float v = di * acc[r] + myrow[c] * self + __ldg(&b[c]);
            if (RELU) v = fmaxf(v, 0.0f);
            out[(size_t)node * N + c] = v;
        }
    }
}

// Final layer (N=1): lanes parallelize over edges; writes d_out.
__global__ void __launch_bounds__(256)
k_gather_out(const float* __restrict__ b, float* __restrict__ out, int n) {
    const int node = (blockIdx.x * blockDim.x + threadIdx.x) >> 5;
    if (node >= n) return;
    const int lane = threadIdx.x & 31;
    const float* xw = (const float*)g_bufA;
    const int beg = g_rowoff[node];
    const int end = g_rowoff[node + 1];
    float acc = 0.0f;
    for (int e = beg + lane; e < end; e += 32) {
        int s = g_csr[e];
        acc += g_dinv[s] * __ldg(&xw[s]);
    }
#pragma unroll
    for (int off = 16; off; off >>= 1) acc += __shfl_down_sync(0xffffffffu, acc, off);
    if (lane == 0) {
        float di = g_dinv[node];
        out[node] = di * acc + xw[node] * di * di + __ldg(&b[0]);
    }
}

// ------------------- launcher (pure kernel launches; capture-safe) -------------------
extern "C" void kernel_launch(void* const* d_in, const int* in_sizes, int n_in,
                              void* d_out, int out_size) {
    const float* x   = (const float*)d_in[0];
    const void*  ei  = d_in[1];
    const float* W1  = (const float*)d_in[2];
    const float* b1  = (const float*)d_in[3];
    const float* W2  = (const float*)d_in[4];
    const float* b2  = (const float*)d_in[5];
    const float* W3  = (const float*)d_in[6];
    const float* b3  = (const float*)d_in[7];
    float*       out = (float*)d_out;

    const int n = in_sizes[0] / IN_C;
    const int E = in_sizes[1] / 2;

    const int TB = 256;
    const int nb_nodes = (n + TB - 1) / TB;
    const int nb_edges = (E + TB - 1) / TB;
    const int nb_warps = (n * 32 + TB - 1) / TB;  // warp per node
    const int nb_gemm  = (n + 255) / 256;

    // Graph structure (recomputed each call; deterministic structure)
    k_sniff<<<1, 32>>>((const int*)ei, E);
    k_init_deg<<<nb_nodes, TB>>>(n);
    k_deg_count<<<nb_edges, TB>>>(ei, E, n);
    k_dinv<<<nb_nodes, TB>>>(n);
    k_scan<<<1, 1024>>>(n);
    k_fill<<<nb_edges, TB>>>(E);

    // Layer 1: x@W1 -> bufA ; gather+bias+relu -> bufB
    k_gemm<IN_C, H1, true><<<nb_gemm, 256>>>(x, W1, n);
    k_gather<H1, true><<<nb_warps, TB>>>(b1, n);

    // Layer 2: bufB@W2 -> bufA ; gather+bias -> bufB
    k_gemm<H1, H2, false><<<nb_gemm, 256>>>(nullptr, W2, n);
    k_gather<H2, false><<<nb_warps, TB>>>(b2, n);

    // Layer 3: bufB@W3 -> bufA (dim 1) ; gather+bias -> out
    k_gemm<H2, 1, false><<<nb_gemm, 256>>>(nullptr, W3, n);
    k_gather_out<<<nb_warps, TB>>>(b3, out, n);
}

// round 4
// speedup vs baseline: 1.3704x; 1.3704x over previous
#include <cuda_runtime.h>
#include <cuda_bf16.h>
#include <math.h>

// Problem constants (from reference)
#define N_NODES_MAX 100000
#define E_MAX       1600000
#define IN_C 128
#define H1   71
#define H2   82
// padded row strides (floats), multiples of 4 for float4 alignment
#define NP1  72   // H1 padded
#define NP2  84   // H2 padded

// ------------------- device scratch (static, no allocation) -------------------
__device__ int   g_is64;
__device__ int   g_deg[N_NODES_MAX];
__device__ float g_dinv[N_NODES_MAX];
__device__ int   g_rowoff[N_NODES_MAX + 1];
__device__ int   g_cursor[N_NODES_MAX];
__device__ int   g_csr[E_MAX];
__device__ int   g_src[E_MAX];
__device__ int   g_dst[E_MAX];
__device__ int   g_bsum[256];
__device__ float g_bufA[(size_t)N_NODES_MAX * NP2];  // GEMM outputs (scaled rows)
__device__ float g_bufB[(size_t)N_NODES_MAX * NP2];  // gather outputs

// ------------------- packed f32x2 helpers -------------------
__device__ __forceinline__ unsigned long long pk2(float lo, float hi) {
    unsigned long long d;
    asm("mov.b64 %0, {%1, %2};" : "=l"(d) : "f"(lo), "f"(hi));
    return d;
}
__device__ __forceinline__ void upk2(float& lo, float& hi, unsigned long long v) {
    asm("mov.b64 {%0, %1}, %2;" : "=f"(lo), "=f"(hi) : "l"(v));
}
#define FMA2(d, a, b, c) \
    asm("fma.rn.f32x2 %0, %1, %2, %3;" : "=l"(d) : "l"(a), "l"(b), "l"(c))
#define MUL2(d, a, b) \
    asm("mul.rn.f32x2 %0, %1, %2;" : "=l"(d) : "l"(a), "l"(b))

// ------------------- setup kernels -------------------
__global__ void k_init_deg(const int* __restrict__ ei32, int E, int n) {
    int i = blockIdx.x * blockDim.x + threadIdx.x;
    if (i < n) g_deg[i] = 0;
    if (blockIdx.x == 0 && threadIdx.x == 0) {
        // dtype sniff: int64 indices < 1e5 have zero odd words
        int all0 = 1;
        int m = (E > 64) ? 64 : E;
        for (int q = 0; q < m; q++)
            if (ei32[2 * q + 1] != 0) { all0 = 0; break; }
        g_is64 = all0;
    }
}

__global__ void k_deg_count(const void* __restrict__ ei, int E, int n) {
    int i = blockIdx.x * blockDim.x + threadIdx.x;
    if (i < E) {
        int s, d;
        if (g_is64) {
            s = (int)((const long long*)ei)[i];
            d = (int)((const long long*)ei)[(size_t)E + i];
        } else {
            s = ((const int*)ei)[i];
            d = ((const int*)ei)[(size_t)E + i];
        }
        s = min(max(s, 0), n - 1);
        d = min(max(d, 0), n - 1);
        g_src[i] = s;
        g_dst[i] = d;
        atomicAdd(&g_deg[d], 1);
    }
}

// pass 1: per-block (1024 elems) sums of deg; also compute dinv.
__global__ void __launch_bounds__(1024) k_scan1(int n) {
    __shared__ int wsum[32];
    int t = threadIdx.x, lane = t & 31, wid = t >> 5;
    int i = blockIdx.x * 1024 + t;
    int v = (i < n) ? g_deg[i] : 0;
    if (i < n) g_dinv[i] = rsqrtf((float)v + 1.0f);
    int x = v;
#pragma unroll
    for (int off = 16; off; off >>= 1) x += __shfl_down_sync(0xffffffffu, x, off);
    if (lane == 0) wsum[wid] = x;
    __syncthreads();
    if (wid == 0) {
        int y = wsum[lane];
#pragma unroll
        for (int off = 16; off; off >>= 1) y += __shfl_down_sync(0xffffffffu, y, off);
        if (lane == 0) g_bsum[blockIdx.x] = y;
    }
}

// pass 2: exclusive scan of block sums (nb <= 256), single block of 256.
__global__ void __launch_bounds__(256) k_scan2(int nb) {
    __shared__ int wsum[8];
    int t = threadIdx.x, lane = t & 31, wid = t >> 5;
    int v = (t < nb) ? g_bsum[t] : 0;
    int x = v;
#pragma unroll
    for (int off = 1; off < 32; off <<= 1) {
        int y = __shfl_up_sync(0xffffffffu, x, off);
        if (lane >= off) x += y;
    }
    if (lane == 31) wsum[wid] = x;
    __syncthreads();
    if (wid == 0 && lane < 8) {
        int w = wsum[lane];
        int xx = w;
#pragma unroll
        for (int off = 1; off < 8; off <<= 1) {
            int y = __shfl_up_sync(0xffu, xx, off);
            if (lane >= off) xx += y;
        }
        wsum[lane] = xx - w;  // exclusive warp offsets
    }
    __syncthreads();
    if (t < nb) g_bsum[t] = wsum[wid] + (x - v);
}

// pass 3: local exclusive scan + block offset -> rowoff, cursor.
__global__ void __launch_bounds__(1024) k_scan3(int n) {
    __shared__ int wsum[32];
    int t = threadIdx.x, lane = t & 31, wid = t >> 5;
    int i = blockIdx.x * 1024 + t;
    int v = (i < n) ? g_deg[i] : 0;
    int x = v;
#pragma unroll
    for (int off = 1; off < 32; off <<= 1) {
        int y = __shfl_up_sync(0xffffffffu, x, off);
        if (lane >= off) x += y;
    }
    if (lane == 31) wsum[wid] = x;
    __syncthreads();
    if (wid == 0) {
        int w = wsum[lane];
        int xx = w;
#pragma unroll
        for (int off = 1; off < 32; off <<= 1) {
            int y = __shfl_up_sync(0xffffffffu, xx, off);
            if (lane >= off) xx += y;
        }
        wsum[lane] = xx - w;
    }
    __syncthreads();
    int excl = g_bsum[blockIdx.x] + wsum[wid] + (x - v);
    if (i < n) {
        g_rowoff[i] = excl;
        g_cursor[i] = excl;
    }
    if (i == n - 1) g_rowoff[n] = excl + v;
}

__global__ void k_fill(int E) {
    int i = blockIdx.x * blockDim.x + threadIdx.x;
    if (i < E) {
        int d = g_dst[i];
        int p = atomicAdd(&g_cursor[d], 1);
        g_csr[p] = g_src[i];
    }
}

// ------------------- GEMM: g_bufA[node, 0..NP) = dinv[node] * (X[node,:] @ W) -------------------
// Packed f32x2 accumulation. Output rows padded to NP (pad cols = 0), stride NP.
template <int KREAL, int KLOOP, int LDX, int NREAL, int NP, bool FROM_PARAM>
__global__ void __launch_bounds__(256)
k_gemm2(const float* __restrict__ Xp, const float* __restrict__ W, int n) {
    constexpr int BM = 256, KK = 32;
    constexpr int NQ = NP / 4, NH = NP / 2;
    __shared__ float  xs[KK][BM + 1];
    __shared__ float4 ws4[KK][NQ];
    const float* X = FROM_PARAM ? Xp : (const float*)g_bufB;
    const int t = threadIdx.x;
    const int node0 = blockIdx.x * BM;

    unsigned long long acc[NH];
#pragma unroll
    for (int h = 0; h < NH; h++) acc[h] = 0ull;

    for (int k0 = 0; k0 < KLOOP; k0 += KK) {
        const int kc = (KLOOP - k0 < KK) ? (KLOOP - k0) : KK;
        // x tile, transposed into smem (coalesced global reads)
        for (int idx = t; idx < BM * KK; idx += 256) {
            int nl = idx >> 5;
            int kk = idx & 31;
            int node = node0 + nl;
            float v = 0.0f;
            if (kk < kc && node < n) v = X[(size_t)node * LDX + k0 + kk];
            xs[kk][nl] = v;
        }
        // W chunk into float4 smem, zero-padded
        for (int idx = t; idx < KK * NQ; idx += 256) {
            int kk = idx / NQ;
            int q = idx - kk * NQ;
            int j = q * 4;
            int gk = k0 + kk;
            float4 w = make_float4(0.f, 0.f, 0.f, 0.f);
            if (gk < KREAL) {
                const float* wr = W + (size_t)gk * NREAL;
                if (j + 0 < NREAL) w.x = wr[j + 0];
                if (j + 1 < NREAL) w.y = wr[j + 1];
                if (j + 2 < NREAL) w.z = wr[j + 2];
                if (j + 3 < NREAL) w.w = wr[j + 3];
            }
            ws4[kk][q] = w;
        }
        __syncthreads();
#pragma unroll 4
        for (int kk = 0; kk < kc; kk++) {
            float xv = xs[kk][t];
            unsigned long long xv2 = pk2(xv, xv);
#pragma unroll
            for (int q = 0; q < NQ; q++) {
                float4 w = ws4[kk][q];
                unsigned long long w01 = pk2(w.x, w.y);
                unsigned long long w23 = pk2(w.z, w.w);
                FMA2(acc[2 * q], xv2, w01, acc[2 * q]);
                FMA2(acc[2 * q + 1], xv2, w23, acc[2 * q + 1]);
            }
        }
        __syncthreads();
    }

    const int node = node0 + t;
    if (node < n) {
        float di = g_dinv[node];
        unsigned long long di2 = pk2(di, di);
        float4* Y4 = (float4*)g_bufA;
#pragma unroll
        for (int q = 0; q < NQ; q++) {
            unsigned long long r0, r1;
            MUL2(r0, acc[2 * q], di2);
            MUL2(r1, acc[2 * q + 1], di2);
            float4 o;
            upk2(o.x, o.y, r0);
            upk2(o.z, o.w, r1);
            Y4[(size_t)node * NQ + q] = o;
        }
    }
}

// Layer-3 GEMM (N=1): y[node] = dinv[node] * (h2[node,:] . W3), smem-tiled x.
__global__ void __launch_bounds__(256)
k_gemm_n1(const float* __restrict__ W, int n) {
    constexpr int BM = 256, KK = 32, KLOOP = NP2, KREAL = H2;
    __shared__ float xs[KK][BM + 1];
    __shared__ float ws[KLOOP];
    const float* X = (const float*)g_bufB;
    const int t = threadIdx.x;
    const int node0 = blockIdx.x * BM;
    if (t < KLOOP) ws[t] = (t < KREAL) ? W[t] : 0.0f;
    __syncthreads();
    float acc = 0.0f;
    for (int k0 = 0; k0 < KLOOP; k0 += KK) {
        const int kc = (KLOOP - k0 < KK) ? (KLOOP - k0) : KK;
        for (int idx = t; idx < BM * KK; idx += 256) {
            int nl = idx >> 5;
            int kk = idx & 31;
            int node = node0 + nl;
            float v = 0.0f;
            if (kk < kc && node < n) v = X[(size_t)node * NP2 + k0 + kk];
            xs[kk][nl] = v;
        }
        __syncthreads();
#pragma unroll 8
        for (int kk = 0; kk < kc; kk++) acc += xs[kk][t] * ws[k0 + kk];
        __syncthreads();
    }
    const int node = node0 + t;
    if (node < n) g_bufA[node] = acc * g_dinv[node];
}

// ------------------- gather: warp/node, one LDG.128 per edge -------------------
// g_bufB[i,:] = dinv[i] * (sum_{s in N(i)} y[s,:] + y[i,:]) + b  (optional relu)
template <int NQ4, int NREAL, bool RELU>
__global__ void __launch_bounds__(256)
k_gather4(const float* __restrict__ b, int n) {
    const int node = (blockIdx.x * blockDim.x + threadIdx.x) >> 5;
    if (node >= n) return;
    const int lane = threadIdx.x & 31;
    const float4* __restrict__ xw = (const float4*)g_bufA;  // row stride NQ4 float4s
    const bool act = lane < NQ4;

    float4 a0 = make_float4(0.f, 0.f, 0.f, 0.f);
    float4 a1 = make_float4(0.f, 0.f, 0.f, 0.f);

    const int beg = g_rowoff[node];
    const int end = g_rowoff[node + 1];
    int e = beg;
    for (; e + 1 < end; e += 2) {
        int s0 = g_csr[e];
        int s1 = g_csr[e + 1];
        if (act) {
            float4 v0 = __ldg(&xw[(size_t)s0 * NQ4 + lane]);
            float4 v1 = __ldg(&xw[(size_t)s1 * NQ4 + lane]);
            a0.x += v0.x; a0.y += v0.y; a0.z += v0.z; a0.w += v0.w;
            a1.x += v1.x; a1.y += v1.y; a1.z += v1.z; a1.w += v1.w;
        }
    }
    if (e < end) {
        int s0 = g_csr[e];
        if (act) {
            float4 v0 = __ldg(&xw[(size_t)s0 * NQ4 + lane]);
            a0.x += v0.x; a0.y += v0.y; a0.z += v0.z; a0.w += v0.w;
        }
    }
    if (act) {
        float4 yi = __ldg(&xw[(size_t)node * NQ4 + lane]);
        a0.x += a1.x + yi.x; a0.y += a1.y + yi.y;
        a0.z += a1.z + yi.z; a0.w += a1.w + yi.w;
        const float di = g_dinv[node];
        const int c = lane * 4;
        float4 bv = make_float4(0.f, 0.f, 0.f, 0.f);
        if (c + 0 < NREAL) bv.x = __ldg(&b[c + 0]);
        if (c + 1 < NREAL) bv.y = __ldg(&b[c + 1]);
        if (c + 2 < NREAL) bv.z = __ldg(&b[c + 2]);
        if (c + 3 < NREAL) bv.w = __ldg(&b[c + 3]);
        float4 v;
        v.x = fmaf(di, a0.x, bv.x);
        v.y = fmaf(di, a0.y, bv.y);
        v.z = fmaf(di, a0.z, bv.z);
        v.w = fmaf(di, a0.w, bv.w);
        if (RELU) {
            v.x = fmaxf(v.x, 0.f); v.y = fmaxf(v.y, 0.f);
            v.z = fmaxf(v.z, 0.f); v.w = fmaxf(v.w, 0.f);
        }
        // force pad cols to zero (keeps next layer's pad-K columns inert)
        if (c + 1 >= NREAL) v.y = (c + 1 < NREAL) ? v.y : ((c + 1 == NREAL) ? 0.f : 0.f);
        if (c + 0 >= NREAL) v.x = 0.f;
        if (c + 1 >= NREAL) v.y = 0.f;
        if (c + 2 >= NREAL) v.z = 0.f;
        if (c + 3 >= NREAL) v.w = 0.f;
        ((float4*)g_bufB)[(size_t)node * NQ4 + lane] = v;
    }
}

// Final layer (scalar): lanes over edges, shfl reduce; writes d_out.
__global__ void __launch_bounds__(256)
k_gather_out(const float* __restrict__ b, float* __restrict__ out, int n) {
    const int node = (blockIdx.x * blockDim.x + threadIdx.x) >> 5;
    if (node >= n) return;
    const int lane = threadIdx.x & 31;
    const float* y = (const float*)g_bufA;  // stride 1, already dinv_s-scaled
    const int beg = g_rowoff[node];
    const int end = g_rowoff[node + 1];
    float acc = 0.0f;
    for (int e = beg + lane; e < end; e += 32) {
        int s = g_csr[e];
        acc += __ldg(&y[s]);
    }
#pragma unroll
    for (int off = 16; off; off >>= 1) acc += __shfl_down_sync(0xffffffffu, acc, off);
    if (lane == 0) {
        out[node] = g_dinv[node] * (acc + y[node]) + __ldg(&b[0]);
    }
}

// ------------------- launcher (pure kernel launches; capture-safe) -------------------
extern "C" void kernel_launch(void* const* d_in, const int* in_sizes, int n_in,
                              void* d_out, int out_size) {
    const float* x   = (const float*)d_in[0];
    const void*  ei  = d_in[1];
    const float* W1  = (const float*)d_in[2];
    const float* b1  = (const float*)d_in[3];
    const float* W2  = (const float*)d_in[4];
    const float* b2  = (const float*)d_in[5];
    const float* W3  = (const float*)d_in[6];
    const float* b3  = (const float*)d_in[7];
    float*       out = (float*)d_out;

    const int n = in_sizes[0] / IN_C;
    const int E = in_sizes[1] / 2;

    const int TB = 256;
    const int nb_nodes = (n + TB - 1) / TB;
    const int nb_edges = (E + TB - 1) / TB;
    const int nb_warps = (n * 32 + TB - 1) / TB;  // warp per node
    const int nb_gemm  = (n + 255) / 256;
    const int nb_scan  = (n + 1023) / 1024;       // <= 256 required

    // CSR build
    k_init_deg<<<nb_nodes, TB>>>((const int*)ei, E, n);
    k_deg_count<<<nb_edges, TB>>>(ei, E, n);
    k_scan1<<<nb_scan, 1024>>>(n);
    k_scan2<<<1, 256>>>(nb_scan);
    k_scan3<<<nb_scan, 1024>>>(n);
    k_fill<<<nb_edges, TB>>>(E);

    // Layer 1: y = dinv*(x@W1)  [stride 72] ; gather+bias+relu -> bufB [stride 72]
    k_gemm2<IN_C, IN_C, IN_C, H1, NP1, true><<<nb_gemm, 256>>>(x, W1, n);
    k_gather4<NP1 / 4, H1, true><<<nb_warps, TB>>>(b1, n);

    // Layer 2: y = dinv*(h1@W2) [stride 84] ; gather+bias -> bufB [stride 84]
    k_gemm2<H1, NP1, NP1, H2, NP2, false><<<nb_gemm, 256>>>(nullptr, W2, n);
    k_gather4<NP2 / 4, H2, false><<<nb_warps, TB>>>(b2, n);

    // Layer 3: y = dinv*(h2@W3) [stride 1] ; gather+bias -> out
    k_gemm_n1<<<nb_gemm, 256>>>(W3, n);
    k_gather_out<<<nb_warps, TB>>>(b3, out, n);
}